// round 5
// baseline (speedup 1.0000x reference)
#include <cuda_runtime.h>
#include <math.h>

#define NB 4
#define NE 100000
#define NT 100000
#define ND 64
#define MAX1 4096
#define MAX2 8192
#define SUPN 128
#define OUTH 512
#define EPSV 1e-6f
#define NB1 128
#define NB2 144
#define THR 256

// ---- persistent device scratch (counters self-reset each launch by tails) ----
__device__ int   g_cnt1 = 0, g_done1 = 0;
__device__ int   g_cnt2 = 0, g_done2 = 0;
__device__ int   g_list1[MAX1];
__device__ int   g_list2[MAX2];
__device__ int   g_nsup;
__device__ int   g_sup[SUPN];            // packed key: e | (b << 17)
__device__ float g_hep[SUPN];
__device__ float g_hhist[SUPN][ND];
__device__ float g_cq[2][NB][ND];

__device__ __forceinline__ float sigm(float x) { return 1.0f / (1.0f + expf(-x)); }

// group-local barrier: 64 threads (2 warps), group gr uses named barrier gr+1
#define GSYNC(gr) asm volatile("bar.sync %0, 64;" :: "r"((gr) + 1) : "memory")

// ============================ K1 ============================
// All blocks: (block 0) cq matmul; scan kb, gather start[b*NE+sub] to collect
// hop-1 triples. Last block: hop-1 GRU (h=0) per entry, smem-hash accumulate
// (ep, hist) per (b, obj), publish support set to globals.
__global__ __launch_bounds__(THR)
void k1(const float* __restrict__ start, const float* __restrict__ rel_emb,
        const float* __restrict__ W_step, const float* __restrict__ b_step,
        const float* __restrict__ w_ih, const float* __restrict__ b_ih,
        const float* __restrict__ b_hh, const float* __restrict__ w_cls,
        const float* __restrict__ b_cls, const int* __restrict__ query,
        const int* __restrict__ kb)
{
    __shared__ int   s_key[SUPN];
    __shared__ float s_hep[SUPN];
    __shared__ float s_hhist[SUPN][ND];
    __shared__ float s_rf[4][ND], s_red[4][ND];
    __shared__ int   s_sidx[4];
    __shared__ float s_p[4];
    __shared__ int   s_last;

    const int tid = blockIdx.x * THR + threadIdx.x;

    // block 0: cq[step][b][:] = tanh(rel_emb[query[b]] @ W_step[step] + b_step[step])
    if (blockIdx.x == 0) {
        for (int o = threadIdx.x; o < 2 * NB * ND; o += THR) {
            int step = o >> 8, rem = o & 255, b = rem >> 6, j = rem & 63;
            int q = query[b];
            float acc = b_step[step * ND + j];
            const float* re = rel_emb + q * ND;
            const float* W  = W_step + step * ND * ND + j;
            #pragma unroll 8
            for (int i = 0; i < ND; i++) acc += re[i] * W[i * ND];
            g_cq[step][b][j] = tanhf(acc);
        }
    }

    // scan: 4 triples per thread via int4; start[] gather identifies hop-1 triples
    const int4* kb4 = (const int4*)kb;
    for (int c = tid; c < NT / 4; c += NB1 * THR) {
        int4 v0 = kb4[3 * c], v1 = kb4[3 * c + 1], v2 = kb4[3 * c + 2];
        int ss[4] = { v0.x, v0.w, v1.z, v2.y };
        #pragma unroll
        for (int j = 0; j < 4; j++) {
            int s = ss[j];
            #pragma unroll
            for (int b = 0; b < NB; b++) {
                if (start[b * NE + s] != 0.0f) {     // one-hot: value is exactly 1.0
                    int i = atomicAdd(&g_cnt1, 1);
                    if (i < MAX1) g_list1[i] = (4 * c + j) * 4 + b;
                }
            }
        }
    }

    __threadfence();
    __syncthreads();
    if (threadIdx.x == 0) s_last = (atomicAdd(&g_done1, 1) == NB1 - 1);
    __syncthreads();
    if (!s_last) return;
    __threadfence();

    // ---- tail: hop-1 GRU with h = 0, accumulate into smem ----
    for (int j = threadIdx.x; j < SUPN; j += THR) { s_key[j] = -1; s_hep[j] = 0.f; }
    for (int j = threadIdx.x; j < SUPN * ND; j += THR) ((float*)s_hhist)[j] = 0.f;
    __syncthreads();

    int n1 = min(__ldcg(&g_cnt1), MAX1);
    int gr = threadIdx.x >> 6, d = threadIdx.x & 63;
    for (int i = gr; i < n1; i += 4) {
        int code = __ldcg(&g_list1[i]);
        int t = code >> 2, b = code & 3;
        int e = __ldcg(&kb[3 * t + 1]), rid = __ldcg(&kb[3 * t + 2]);

        s_rf[gr][d] = rel_emb[rid * ND + d];
        GSYNC(gr);

        float xr = b_ih[d], xz = b_ih[ND + d], xn = b_ih[2 * ND + d];
        const float* wr = w_ih + d * ND;
        const float* wz = w_ih + (ND + d) * ND;
        const float* wn = w_ih + (2 * ND + d) * ND;
        #pragma unroll 8
        for (int k = 0; k < ND; k++) {
            float f = s_rf[gr][k];
            xr += f * wr[k]; xz += f * wz[k]; xn += f * wn[k];
        }
        float r  = sigm(xr + b_hh[d]);
        float z  = sigm(xz + b_hh[ND + d]);
        float nn = tanhf(xn + r * b_hh[2 * ND + d]);
        float trans = (1.0f - z) * nn;                    // h = 0

        s_red[gr][d] = trans * __ldcg(&g_cq[0][b][d]) * w_cls[d];
        GSYNC(gr);
        if (d < 32) {
            float v = s_red[gr][d] + s_red[gr][d + 32];
            #pragma unroll
            for (int off = 16; off > 0; off >>= 1)
                v += __shfl_down_sync(0xffffffffu, v, off);
            if (d == 0) {
                float p = sigm(v + b_cls[0]);             // obj_p = 1 * p
                int key = e | (b << 17);
                int sidx = 0;
                for (int j = 0; j < SUPN; j++) {
                    int prev = atomicCAS(&s_key[j], -1, key);
                    if (prev == -1 || prev == key) { sidx = j; break; }
                }
                s_sidx[gr] = sidx; s_p[gr] = p;
                atomicAdd(&s_hep[sidx], p);
            }
        }
        GSYNC(gr);
        atomicAdd(&s_hhist[s_sidx[gr]][d], trans * s_p[gr]);
        GSYNC(gr);
    }
    __syncthreads();

    // publish support set + reset counters for next launch
    if (threadIdx.x == 0) {
        int ns = 0;
        while (ns < SUPN && s_key[ns] != -1) ns++;        // slots fill contiguously
        g_nsup = ns;
        g_cnt1 = 0; g_done1 = 0;
    }
    for (int j = threadIdx.x; j < SUPN; j += THR) {
        g_sup[j] = s_key[j]; g_hep[j] = s_hep[j];
    }
    for (int j = threadIdx.x; j < SUPN * ND; j += THR)
        ((float*)g_hhist)[j] = ((float*)s_hhist)[j];
}

// ============================ K2 ============================
// All blocks: zero out; scan kb vs smem support list to collect hop-2 triples.
// Last block: hop-2 full GRU per entry, smem-hash accumulate, write clamped out.
__global__ __launch_bounds__(THR)
void k2(const float* __restrict__ rel_emb, const float* __restrict__ w_ih,
        const float* __restrict__ w_hh, const float* __restrict__ b_ih,
        const float* __restrict__ b_hh, const float* __restrict__ w_cls,
        const float* __restrict__ b_cls, const int* __restrict__ kb,
        float* __restrict__ out)
{
    __shared__ int   s_sup[SUPN];
    __shared__ int   s_ns;
    __shared__ float s_rf[4][ND], s_h[4][ND], s_red[4][ND];
    __shared__ int   s_sidx[4];
    __shared__ int   s_okey[OUTH];
    __shared__ float s_oval[OUTH];
    __shared__ int   s_last;

    const int tid = blockIdx.x * THR + threadIdx.x;

    if (threadIdx.x == 0) s_ns = min(__ldcg(&g_nsup), SUPN);
    __syncthreads();
    const int ns = s_ns;
    for (int j = threadIdx.x; j < ns; j += THR) s_sup[j] = __ldcg(&g_sup[j]);
    __syncthreads();

    // zero output (poisoned by harness)
    float4* out4 = (float4*)out;
    for (int i = tid; i < (NB * NE) / 4; i += NB2 * THR)
        out4[i] = make_float4(0.f, 0.f, 0.f, 0.f);

    // scan kb vs support list
    const int4* kb4 = (const int4*)kb;
    for (int c = tid; c < NT / 4; c += NB2 * THR) {
        int4 v0 = kb4[3 * c], v1 = kb4[3 * c + 1], v2 = kb4[3 * c + 2];
        int ss[4] = { v0.x, v0.w, v1.z, v2.y };
        #pragma unroll
        for (int j = 0; j < 4; j++) {
            int s = ss[j];
            for (int k = 0; k < ns; k++) {
                int p = s_sup[k];
                if ((p & 0x1FFFF) == s) {
                    int i = atomicAdd(&g_cnt2, 1);
                    if (i < MAX2) g_list2[i] = ((4 * c + j) << 2) | (p >> 17);
                }
            }
        }
    }

    __threadfence();
    __syncthreads();
    if (threadIdx.x == 0) s_last = (atomicAdd(&g_done2, 1) == NB2 - 1);
    __syncthreads();
    if (!s_last) return;
    __threadfence();

    // ---- tail: hop-2 full GRU ----
    for (int j = threadIdx.x; j < OUTH; j += THR) { s_okey[j] = -1; s_oval[j] = 0.f; }
    __syncthreads();

    int n2 = min(__ldcg(&g_cnt2), MAX2);
    int gr = threadIdx.x >> 6, d = threadIdx.x & 63;
    for (int i = gr; i < n2; i += 4) {
        int code = __ldcg(&g_list2[i]);
        int t = code >> 2, b = code & 3;
        int s = __ldcg(&kb[3 * t]), e = __ldcg(&kb[3 * t + 1]), rid = __ldcg(&kb[3 * t + 2]);

        if (d == 0) {
            int key = s | (b << 17);
            int si = 0;
            for (int k = 0; k < ns; k++) if (s_sup[k] == key) { si = k; break; }
            s_sidx[gr] = si;
        }
        GSYNC(gr);
        int si = s_sidx[gr];
        float ep = __ldcg(&g_hep[si]);
        s_h[gr][d]  = __ldcg(&g_hhist[si][d]) / (ep + EPSV);
        s_rf[gr][d] = rel_emb[rid * ND + d];
        GSYNC(gr);

        float xr = b_ih[d], xz = b_ih[ND + d], xn = b_ih[2 * ND + d];
        float hr = b_hh[d], hz = b_hh[ND + d], hn = b_hh[2 * ND + d];
        const float* wir = w_ih + d * ND;
        const float* wiz = w_ih + (ND + d) * ND;
        const float* win = w_ih + (2 * ND + d) * ND;
        const float* whr = w_hh + d * ND;
        const float* whz = w_hh + (ND + d) * ND;
        const float* whn = w_hh + (2 * ND + d) * ND;
        #pragma unroll 4
        for (int k = 0; k < ND; k++) {
            float f = s_rf[gr][k], hh = s_h[gr][k];
            xr += f * wir[k]; xz += f * wiz[k]; xn += f * win[k];
            hr += hh * whr[k]; hz += hh * whz[k]; hn += hh * whn[k];
        }
        float r  = sigm(xr + hr);
        float z  = sigm(xz + hz);
        float nn = tanhf(xn + r * hn);
        float trans = (1.0f - z) * nn + z * s_h[gr][d];

        s_red[gr][d] = trans * __ldcg(&g_cq[1][b][d]) * w_cls[d];
        GSYNC(gr);
        if (d < 32) {
            float v = s_red[gr][d] + s_red[gr][d + 32];
            #pragma unroll
            for (int off = 16; off > 0; off >>= 1)
                v += __shfl_down_sync(0xffffffffu, v, off);
            if (d == 0) {
                float p = sigm(v + b_cls[0]);
                float contrib = fminf(ep, 1.0f) * p;      // last_e0 * trans_prob
                int key = b * NE + e;
                unsigned h = ((unsigned)key * 2654435761u) & (OUTH - 1);
                for (;;) {
                    int prev = atomicCAS(&s_okey[h], -1, key);
                    if (prev == -1 || prev == key) break;
                    h = (h + 1) & (OUTH - 1);
                }
                atomicAdd(&s_oval[h], contrib);
            }
        }
        GSYNC(gr);
    }
    __syncthreads();

    // write clamped results (last_e = min(obj_ep, 1)); reset counters
    for (int j = threadIdx.x; j < OUTH; j += THR) {
        int k = s_okey[j];
        if (k >= 0) out[k] = fminf(s_oval[j], 1.0f);
    }
    if (threadIdx.x == 0) { g_cnt2 = 0; g_done2 = 0; }
}

extern "C" void kernel_launch(void* const* d_in, const int* in_sizes, int n_in,
                              void* d_out, int out_size)
{
    const float* start   = (const float*)d_in[0];
    const float* rel_emb = (const float*)d_in[1];
    const float* W_step  = (const float*)d_in[2];
    const float* b_step  = (const float*)d_in[3];
    const float* w_ih    = (const float*)d_in[4];
    const float* w_hh    = (const float*)d_in[5];
    const float* b_ih    = (const float*)d_in[6];
    const float* b_hh    = (const float*)d_in[7];
    const float* w_cls   = (const float*)d_in[8];
    const float* b_cls   = (const float*)d_in[9];
    const int*   query   = (const int*)d_in[10];
    const int*   kb      = (const int*)d_in[11];
    float* out = (float*)d_out;

    k1<<<NB1, THR>>>(start, rel_emb, W_step, b_step, w_ih, b_ih, b_hh,
                     w_cls, b_cls, query, kb);
    k2<<<NB2, THR>>>(rel_emb, w_ih, w_hh, b_ih, b_hh, w_cls, b_cls, kb, out);
}

// round 11
// speedup vs baseline: 2.3387x; 2.3387x over previous
#include <cuda_runtime.h>
#include <math.h>

#define NB 4
#define NE 100000
#define NT 100000
#define ND 64
#define HSZ 256          // hop-1 (b,obj) hash, direct-slot; key stored +1, 0 = empty
#define HSZ2 1024        // output hash; key stored +1, 0 = empty
#define SUPN 128
#define EPSV 1e-6f
#define FULLM 0xffffffffu

// ---- persistent scratch. .bss zeros == cleared state; K3 re-clears each launch ----
__device__ int   g_s0[NB];
__device__ float g_cq[2][NB][ND];
__device__ int   g_nsup;
__device__ int   g_supk[SUPN];     // packed (b<<17)|e
__device__ int   g_sups[SUPN];     // hash slot holding (ep, hist)
__device__ int   g_hkey[HSZ];
__device__ float g_hep[HSZ];
__device__ float g_hhist[HSZ][ND];
__device__ int   g_h2key[HSZ2];
__device__ float g_h2ep[HSZ2];

__device__ __forceinline__ float sigm(float x) { return 1.0f / (1.0f + expf(-x)); }

// ================= K0: out zero + start one-hot scan + cq matmul =================
__global__ void k0(const float4* __restrict__ start4, float4* __restrict__ out4,
                   const float* __restrict__ rel_emb, const float* __restrict__ W_step,
                   const float* __restrict__ b_step, const int* __restrict__ query)
{
    int idx = blockIdx.x * 256 + threadIdx.x;          // 0 .. 100352
    if (idx < (NB * NE) / 4) {
        out4[idx] = make_float4(0.f, 0.f, 0.f, 0.f);
        float4 s = start4[idx];
        if (s.x != 0.f || s.y != 0.f || s.z != 0.f || s.w != 0.f) {
            int b  = idx / (NE / 4);
            int p0 = idx * 4 - b * NE;
            if (s.x != 0.f) g_s0[b] = p0;
            if (s.y != 0.f) g_s0[b] = p0 + 1;
            if (s.z != 0.f) g_s0[b] = p0 + 2;
            if (s.w != 0.f) g_s0[b] = p0 + 3;
        }
    }
    // block 0: cq[step][b][d] = tanh(rel_emb[query[b]] . W_step[step][:,d] + b_step[step][d])
    if (blockIdx.x == 0) {
        for (int o = threadIdx.x; o < 2 * NB * ND; o += 256) {
            int step = o >> 8, rem = o & 255, b = rem >> 6, d = rem & 63;
            int q = query[b];
            float acc = b_step[step * ND + d];
            const float* re = rel_emb + q * ND;
            const float* W  = W_step + step * ND * ND + d;
            #pragma unroll 8
            for (int i = 0; i < ND; i++) acc += re[i] * W[i * ND];
            g_cq[step][b][d] = tanhf(acc);
        }
    }
}

// ================= warp-cooperative hop-1 GRU (h = 0), 2 features/lane =================
__device__ __forceinline__ void warp_hop1(int t, int b, int lane,
    const int* __restrict__ kb, const float* __restrict__ rel_emb,
    const float* __restrict__ w_ih, const float* __restrict__ b_ih,
    const float* __restrict__ b_hh, const float* __restrict__ w_cls,
    const float* __restrict__ b_cls)
{
    int e = kb[3 * t + 1], rid = kb[3 * t + 2];
    int d0 = lane, d1 = lane + 32;
    float rf0 = rel_emb[rid * ND + d0];
    float rf1 = rel_emb[rid * ND + d1];
    float a0 = b_ih[d0], a1 = b_ih[ND + d0], a2 = b_ih[2 * ND + d0];
    float a3 = b_ih[d1], a4 = b_ih[ND + d1], a5 = b_ih[2 * ND + d1];
    const float* w0 = w_ih + d0 * ND;
    const float* w1 = w_ih + (ND + d0) * ND;
    const float* w2 = w_ih + (2 * ND + d0) * ND;
    const float* w3 = w_ih + d1 * ND;
    const float* w4 = w_ih + (ND + d1) * ND;
    const float* w5 = w_ih + (2 * ND + d1) * ND;
    #pragma unroll
    for (int k = 0; k < ND; k++) {
        float f = __shfl_sync(FULLM, (k < 32) ? rf0 : rf1, k & 31);
        a0 += f * w0[k]; a1 += f * w1[k]; a2 += f * w2[k];
        a3 += f * w3[k]; a4 += f * w4[k]; a5 += f * w5[k];
    }
    float r0 = sigm(a0 + b_hh[d0]);
    float z0 = sigm(a1 + b_hh[ND + d0]);
    float n0 = tanhf(a2 + r0 * b_hh[2 * ND + d0]);
    float tr0 = (1.f - z0) * n0;                        // h = 0
    float r1 = sigm(a3 + b_hh[d1]);
    float z1 = sigm(a4 + b_hh[ND + d1]);
    float n1 = tanhf(a5 + r1 * b_hh[2 * ND + d1]);
    float tr1 = (1.f - z1) * n1;

    float red = tr0 * g_cq[0][b][d0] * w_cls[d0]
              + tr1 * g_cq[0][b][d1] * w_cls[d1];
    #pragma unroll
    for (int off = 16; off; off >>= 1) red += __shfl_xor_sync(FULLM, red, off);
    float p = sigm(red + b_cls[0]);                     // obj_p = 1 * p

    int slot = 0;
    if (lane == 0) {
        int key1 = b * NE + e + 1;                      // +1: 0 means empty
        unsigned h = ((unsigned)key1 * 2654435761u) & (HSZ - 1);
        for (;;) {
            int prev = atomicCAS(&g_hkey[h], 0, key1);
            if (prev == 0) {
                int j = atomicAdd(&g_nsup, 1);
                if (j < SUPN) { g_supk[j] = (b << 17) | e; g_sups[j] = (int)h; }
                slot = (int)h; break;
            }
            if (prev == key1) { slot = (int)h; break; }
            h = (h + 1) & (HSZ - 1);
        }
        atomicAdd(&g_hep[slot], p);
    }
    slot = __shfl_sync(FULLM, slot, 0);
    atomicAdd(&g_hhist[slot][d0], tr0 * p);
    atomicAdd(&g_hhist[slot][d1], tr1 * p);
}

// ================= K1: kb scan vs start entities + inline hop-1 GRU =================
__global__ void k1(const int* __restrict__ kb, const float* __restrict__ rel_emb,
                   const float* __restrict__ w_ih, const float* __restrict__ b_ih,
                   const float* __restrict__ b_hh, const float* __restrict__ w_cls,
                   const float* __restrict__ b_cls)
{
    int c = blockIdx.x * 256 + threadIdx.x;             // chunk of 4 triples
    int lane = threadIdx.x & 31;
    bool valid = c < NT / 4;
    int a0 = g_s0[0], a1 = g_s0[1], a2 = g_s0[2], a3 = g_s0[3];
    int ss0 = -1, ss1 = -1, ss2 = -1, ss3 = -1;
    if (valid) {
        const int4* kb4 = (const int4*)kb;
        int4 v0 = kb4[3 * c], v1 = kb4[3 * c + 1], v2 = kb4[3 * c + 2];
        ss0 = v0.x; ss1 = v0.w; ss2 = v1.z; ss3 = v2.y;
    }
    int ssa[4] = { ss0, ss1, ss2, ss3 };
    #pragma unroll
    for (int j = 0; j < 4; j++) {
        int s = ssa[j];
        int t_mine = 4 * c + j;
        #pragma unroll
        for (int b = 0; b < NB; b++) {
            int sb = (b == 0) ? a0 : (b == 1) ? a1 : (b == 2) ? a2 : a3;
            unsigned m = __ballot_sync(FULLM, valid && s == sb);
            while (m) {
                int src = __ffs(m) - 1; m &= m - 1;
                int t = __shfl_sync(FULLM, t_mine, src);
                warp_hop1(t, b, lane, kb, rel_emb, w_ih, b_ih, b_hh, w_cls, b_cls);
            }
        }
    }
}

// ================= warp-cooperative hop-2 full GRU =================
__device__ __forceinline__ void warp_hop2(int t, int b, int slot, int lane,
    const int* __restrict__ kb, const float* __restrict__ rel_emb,
    const float* __restrict__ w_ih, const float* __restrict__ w_hh,
    const float* __restrict__ b_ih, const float* __restrict__ b_hh,
    const float* __restrict__ w_cls, const float* __restrict__ b_cls)
{
    int e = kb[3 * t + 1], rid = kb[3 * t + 2];
    int d0 = lane, d1 = lane + 32;
    float ep = g_hep[slot];
    float rf0 = rel_emb[rid * ND + d0];
    float rf1 = rel_emb[rid * ND + d1];
    float h0 = g_hhist[slot][d0] / (ep + EPSV);
    float h1 = g_hhist[slot][d1] / (ep + EPSV);

    float x0 = b_ih[d0], x1 = b_ih[ND + d0], x2 = b_ih[2 * ND + d0];
    float x3 = b_ih[d1], x4 = b_ih[ND + d1], x5 = b_ih[2 * ND + d1];
    float y0 = b_hh[d0], y1 = b_hh[ND + d0], y2 = b_hh[2 * ND + d0];
    float y3 = b_hh[d1], y4 = b_hh[ND + d1], y5 = b_hh[2 * ND + d1];
    const float* wi0 = w_ih + d0 * ND;
    const float* wi1 = w_ih + (ND + d0) * ND;
    const float* wi2 = w_ih + (2 * ND + d0) * ND;
    const float* wi3 = w_ih + d1 * ND;
    const float* wi4 = w_ih + (ND + d1) * ND;
    const float* wi5 = w_ih + (2 * ND + d1) * ND;
    const float* wh0 = w_hh + d0 * ND;
    const float* wh1 = w_hh + (ND + d0) * ND;
    const float* wh2 = w_hh + (2 * ND + d0) * ND;
    const float* wh3 = w_hh + d1 * ND;
    const float* wh4 = w_hh + (ND + d1) * ND;
    const float* wh5 = w_hh + (2 * ND + d1) * ND;
    #pragma unroll
    for (int k = 0; k < ND; k++) {
        float f  = __shfl_sync(FULLM, (k < 32) ? rf0 : rf1, k & 31);
        float hh = __shfl_sync(FULLM, (k < 32) ? h0  : h1,  k & 31);
        x0 += f * wi0[k]; x1 += f * wi1[k]; x2 += f * wi2[k];
        x3 += f * wi3[k]; x4 += f * wi4[k]; x5 += f * wi5[k];
        y0 += hh * wh0[k]; y1 += hh * wh1[k]; y2 += hh * wh2[k];
        y3 += hh * wh3[k]; y4 += hh * wh4[k]; y5 += hh * wh5[k];
    }
    float r0 = sigm(x0 + y0), z0 = sigm(x1 + y1);
    float n0 = tanhf(x2 + r0 * y2);
    float tr0 = (1.f - z0) * n0 + z0 * h0;
    float r1 = sigm(x3 + y3), z1 = sigm(x4 + y4);
    float n1 = tanhf(x5 + r1 * y5);
    float tr1 = (1.f - z1) * n1 + z1 * h1;

    float red = tr0 * g_cq[1][b][d0] * w_cls[d0]
              + tr1 * g_cq[1][b][d1] * w_cls[d1];
    #pragma unroll
    for (int off = 16; off; off >>= 1) red += __shfl_xor_sync(FULLM, red, off);

    if (lane == 0) {
        float p = sigm(red + b_cls[0]);
        float contrib = fminf(ep, 1.f) * p;             // last_e0 * trans_prob
        int key1 = b * NE + e + 1;
        unsigned h = ((unsigned)key1 * 2654435761u) & (HSZ2 - 1);
        for (;;) {
            int prev = atomicCAS(&g_h2key[h], 0, key1);
            if (prev == 0 || prev == key1) break;
            h = (h + 1) & (HSZ2 - 1);
        }
        atomicAdd(&g_h2ep[h], contrib);
    }
}

// ================= K2: kb scan vs support list + inline hop-2 GRU =================
__global__ void k2(const int* __restrict__ kb, const float* __restrict__ rel_emb,
                   const float* __restrict__ w_ih, const float* __restrict__ w_hh,
                   const float* __restrict__ b_ih, const float* __restrict__ b_hh,
                   const float* __restrict__ w_cls, const float* __restrict__ b_cls)
{
    __shared__ int sh_k[SUPN], sh_s[SUPN], sh_ns;
    if (threadIdx.x == 0) sh_ns = min(g_nsup, SUPN);
    __syncthreads();
    int ns = sh_ns;
    for (int j = threadIdx.x; j < ns; j += 256) { sh_k[j] = g_supk[j]; sh_s[j] = g_sups[j]; }
    __syncthreads();

    int c = blockIdx.x * 256 + threadIdx.x;
    int lane = threadIdx.x & 31;
    bool valid = c < NT / 4;
    int ss0 = -1, ss1 = -1, ss2 = -1, ss3 = -1;
    if (valid) {
        const int4* kb4 = (const int4*)kb;
        int4 v0 = kb4[3 * c], v1 = kb4[3 * c + 1], v2 = kb4[3 * c + 2];
        ss0 = v0.x; ss1 = v0.w; ss2 = v1.z; ss3 = v2.y;
    }
    int ssa[4] = { ss0, ss1, ss2, ss3 };
    #pragma unroll
    for (int j = 0; j < 4; j++) {
        int s = ssa[j];
        int t_mine = 4 * c + j;
        for (int k = 0; k < ns; k++) {
            int key = sh_k[k];
            unsigned m = __ballot_sync(FULLM, valid && s == (key & 0x1FFFF));
            while (m) {
                int src = __ffs(m) - 1; m &= m - 1;
                int t = __shfl_sync(FULLM, t_mine, src);
                warp_hop2(t, key >> 17, sh_s[k], lane, kb, rel_emb,
                          w_ih, w_hh, b_ih, b_hh, w_cls, b_cls);
            }
        }
    }
}

// ========== K3: scatter hash2 -> out (clamped) + clear ALL scratch for next launch ==========
__global__ void k3(float* __restrict__ out)
{
    int i = blockIdx.x * 256 + threadIdx.x;             // 0 .. 16383
    if (i < HSZ2) {
        int k1v = g_h2key[i];
        if (k1v) {
            out[k1v - 1] = fminf(g_h2ep[i], 1.f);       // last_e = min(obj_ep, 1)
            g_h2key[i] = 0; g_h2ep[i] = 0.f;
        }
    }
    if (i < HSZ) { g_hkey[i] = 0; g_hep[i] = 0.f; }
    if (i < HSZ * ND) ((float*)g_hhist)[i] = 0.f;
    if (i == 0) g_nsup = 0;
}

extern "C" void kernel_launch(void* const* d_in, const int* in_sizes, int n_in,
                              void* d_out, int out_size)
{
    const float* start   = (const float*)d_in[0];
    const float* rel_emb = (const float*)d_in[1];
    const float* W_step  = (const float*)d_in[2];
    const float* b_step  = (const float*)d_in[3];
    const float* w_ih    = (const float*)d_in[4];
    const float* w_hh    = (const float*)d_in[5];
    const float* b_ih    = (const float*)d_in[6];
    const float* b_hh    = (const float*)d_in[7];
    const float* w_cls   = (const float*)d_in[8];
    const float* b_cls   = (const float*)d_in[9];
    const int*   query   = (const int*)d_in[10];
    const int*   kb      = (const int*)d_in[11];
    float* out = (float*)d_out;

    k0<<<392, 256>>>((const float4*)start, (float4*)out, rel_emb, W_step, b_step, query);
    k1<<<98, 256>>>(kb, rel_emb, w_ih, b_ih, b_hh, w_cls, b_cls);
    k2<<<98, 256>>>(kb, rel_emb, w_ih, w_hh, b_ih, b_hh, w_cls, b_cls);
    k3<<<64, 256>>>(out);
}